// round 1
// baseline (speedup 1.0000x reference)
#include <cuda_runtime.h>
#include <cstdint>

// TokenPooling: out[b,0,:] = x[b,0,:]; out[b,1+j,:] = x[b, 1+topk_idx[b,j], :]
// where topk_idx = indices of the 1024 largest significance values, ordered by
// descending value (ascending index on ties), matching jax.lax.top_k.

#define BB 32
#define NN 4096
#define DD 768
#define KK 1024

__device__ int g_topk[BB * KK];

// Map float to a uint whose ascending unsigned order == ascending float order.
__device__ __forceinline__ unsigned f2ord(float f) {
    unsigned u = __float_as_uint(f);
    return (u & 0x80000000u) ? ~u : (u | 0x80000000u);
}

// One CTA per batch. Build 64-bit keys: high = ~ord(val) (so ascending u64 sort
// = descending value), low = index (ascending tie-break). Full bitonic sort of
// 4096 keys in 32KB smem, then emit first K indices.
__global__ __launch_bounds__(1024) void topk_sort_kernel(const float* __restrict__ sig) {
    __shared__ unsigned long long key[NN];
    const int b = blockIdx.x;
    const int tid = threadIdx.x;
    const float* s = sig + (size_t)b * NN;

    #pragma unroll
    for (int i = tid; i < NN; i += 1024) {
        unsigned inv = ~f2ord(s[i]);
        key[i] = ((unsigned long long)inv << 32) | (unsigned)i;
    }
    __syncthreads();

    for (int k = 2; k <= NN; k <<= 1) {
        for (int j = k >> 1; j > 0; j >>= 1) {
            #pragma unroll
            for (int i = tid; i < NN; i += 1024) {
                int ixj = i ^ j;
                if (ixj > i) {
                    unsigned long long a = key[i];
                    unsigned long long c = key[ixj];
                    // ascending when (i & k) == 0
                    bool swap = ((i & k) == 0) ? (a > c) : (a < c);
                    if (swap) { key[i] = c; key[ixj] = a; }
                }
            }
            __syncthreads();
        }
    }

    if (tid < KK)
        g_topk[b * KK + tid] = (int)(key[tid] & 0xFFFFFFFFu);
}

// One CTA per output row. 192 threads x float4 = 768 floats = 3072 bytes/row.
__global__ __launch_bounds__(192) void gather_kernel(const float4* __restrict__ x,
                                                     float4* __restrict__ out) {
    const int row = blockIdx.x;                 // [0, BB*(KK+1))
    const int b = row / (KK + 1);
    const int r = row - b * (KK + 1);

    int src_row = (r == 0) ? 0 : (1 + g_topk[b * KK + (r - 1)]);

    const float4* src = x + ((size_t)b * (NN + 1) + (size_t)src_row) * (DD / 4);
    float4* dst = out + (size_t)row * (DD / 4);
    dst[threadIdx.x] = src[threadIdx.x];
}

extern "C" void kernel_launch(void* const* d_in, const int* in_sizes, int n_in,
                              void* d_out, int out_size) {
    const float* x   = (const float*)d_in[0];        // [B, N+1, D] fp32
    const float* sig = (const float*)d_in[1];        // [B, N] fp32
    // d_in[2] = keep_tokens (1024, compile-time constant here)
    (void)in_sizes; (void)n_in; (void)out_size;

    topk_sort_kernel<<<BB, 1024>>>(sig);
    gather_kernel<<<BB * (KK + 1), 192>>>((const float4*)x, (float4*)d_out);
}

// round 2
// speedup vs baseline: 1.2412x; 1.2412x over previous
#include <cuda_runtime.h>
#include <cstdint>

#define BB 32
#define NN 4096
#define DD 768
#define KK 1024
#define ROWS_PER_BLK 8

typedef unsigned long long u64;

__device__ int g_topk[BB * KK];

// Map float to uint with ascending unsigned order == ascending float order.
__device__ __forceinline__ unsigned f2ord(float f) {
    unsigned u = __float_as_uint(f);
    return (u & 0x80000000u) ? ~u : (u | 0x80000000u);
}

__device__ __forceinline__ void cswap(u64& a, u64& b, bool desc) {
    // a sits at the lower global index of the pair
    bool sw = desc ? (a < b) : (a > b);
    if (sw) { u64 t = a; a = b; b = t; }
}

// Register-blocked bitonic sort of 4096 composite keys, descending.
// key = (ord(val) << 12) | (4095 - idx)  => top-k by (val desc, idx asc).
// Thread t owns global indices i = 4t..4t+3 in registers.
//   j in {1,2}   : in-register compare-exchange
//   j in {4..64} : warp shfl_xor (lane mask j/4), no block barrier
//   j >= 128     : smem exchange + __syncthreads (only 15 of 78 steps)
__global__ __launch_bounds__(1024) void topk_sort_kernel(const float* __restrict__ sig) {
    __shared__ u64 sm[NN];
    const int t = threadIdx.x;
    const int b = blockIdx.x;
    const int i0 = 4 * t;

    u64 r[4];
    {
        float4 v = ((const float4*)(sig + (size_t)b * NN))[t];
        r[0] = ((u64)f2ord(v.x) << 12) | (u64)(4095 - (i0 + 0));
        r[1] = ((u64)f2ord(v.y) << 12) | (u64)(4095 - (i0 + 1));
        r[2] = ((u64)f2ord(v.z) << 12) | (u64)(4095 - (i0 + 2));
        r[3] = ((u64)f2ord(v.w) << 12) | (u64)(4095 - (i0 + 3));
    }

    for (int k = 2; k <= NN; k <<= 1) {
        for (int j = k >> 1; j > 0; j >>= 1) {
            if (j >= 128) {
                __syncthreads();                 // prior smem reads complete
                #pragma unroll
                for (int e = 0; e < 4; e++) sm[i0 + e] = r[e];
                __syncthreads();
                // k >= 256, j >= 128: direction/lower uniform across e
                bool d        = ((i0 & k) == 0);
                bool lower    = ((i0 & j) == 0);
                bool keep_max = (d == lower);
                #pragma unroll
                for (int e = 0; e < 4; e++) {
                    u64 o = sm[(i0 + e) ^ j];
                    r[e] = keep_max ? (r[e] > o ? r[e] : o)
                                    : (r[e] < o ? r[e] : o);
                }
            } else if (j >= 4) {
                int  m        = j >> 2;          // lane xor mask, 1..16
                bool d        = ((i0 & k) == 0); // k >= 8: uniform across e
                bool lower    = ((t & m) == 0);
                bool keep_max = (d == lower);
                #pragma unroll
                for (int e = 0; e < 4; e++) {
                    u64 o = __shfl_xor_sync(0xffffffffu, r[e], m);
                    r[e] = keep_max ? (r[e] > o ? r[e] : o)
                                    : (r[e] < o ? r[e] : o);
                }
            } else if (j == 2) {
                bool d0 = (((i0 + 0) & k) == 0);
                bool d1 = (((i0 + 1) & k) == 0);
                cswap(r[0], r[2], d0);
                cswap(r[1], r[3], d1);
            } else {  // j == 1
                bool d0 = (((i0 + 0) & k) == 0);
                bool d2 = (((i0 + 2) & k) == 0);
                cswap(r[0], r[1], d0);
                cswap(r[2], r[3], d2);
            }
        }
    }

    if (t < KK / 4) {
        #pragma unroll
        for (int e = 0; e < 4; e++)
            g_topk[b * KK + i0 + e] = 4095 - (int)(r[e] & 0xFFFu);
    }
}

// Gather: 8 rows per CTA, 192 threads (one float4 column each), MLP=8.
__global__ __launch_bounds__(192) void gather_kernel(const float4* __restrict__ x,
                                                     float4* __restrict__ out) {
    const int base = blockIdx.x * ROWS_PER_BLK;
    const int tid  = threadIdx.x;

    const float4* srcs[ROWS_PER_BLK];
    #pragma unroll
    for (int r = 0; r < ROWS_PER_BLK; r++) {
        int row = base + r;
        int b   = row / (KK + 1);
        int rr  = row - b * (KK + 1);
        int src_row = (rr == 0) ? 0 : (1 + g_topk[b * KK + rr - 1]);
        srcs[r] = x + ((size_t)b * (NN + 1) + (size_t)src_row) * (DD / 4);
    }

    float4 vals[ROWS_PER_BLK];
    #pragma unroll
    for (int r = 0; r < ROWS_PER_BLK; r++)
        vals[r] = __ldcs(srcs[r] + tid);        // 8 independent streaming loads

    #pragma unroll
    for (int r = 0; r < ROWS_PER_BLK; r++)
        out[(size_t)(base + r) * (DD / 4) + tid] = vals[r];
}

extern "C" void kernel_launch(void* const* d_in, const int* in_sizes, int n_in,
                              void* d_out, int out_size) {
    const float* x   = (const float*)d_in[0];   // [B, N+1, D] fp32
    const float* sig = (const float*)d_in[1];   // [B, N] fp32
    (void)in_sizes; (void)n_in; (void)out_size;

    topk_sort_kernel<<<BB, 1024>>>(sig);
    gather_kernel<<<BB * (KK + 1) / ROWS_PER_BLK, 192>>>((const float4*)x, (float4*)d_out);
}